// round 3
// baseline (speedup 1.0000x reference)
#include <cuda_runtime.h>
#include <math.h>

// Problem constants
#define H   1024
#define FF  4096
#define E   8
#define T   2048

// GEMM tiling
#define BM  128
#define BN  64
#define BK  16
#define KP  20          // padded smem row stride (floats): bank-conflict-free fragments

// -------- device scratch (no allocations allowed) --------
__device__ int   g_cnt[E];
__device__ int   g_tok[E * T];           // token index per (expert, slot)
__device__ int   g_prow[E * T];          // hact row id = 2*t + k
__device__ float g_w[E * T];             // normalized routing weight
__device__ float g_hact[(size_t)2 * T * FF];   // [4096][4096] fp32 = 64 MB

// -------- helpers --------
__device__ __forceinline__ unsigned f2tf(float x) {
    unsigned u;
    asm("cvt.rna.tf32.f32 %0, %1;" : "=r"(u) : "f"(x));
    return u;
}
__device__ __forceinline__ float4 cv4(float4 v) {
    float4 o;
    o.x = __uint_as_float(f2tf(v.x));
    o.y = __uint_as_float(f2tf(v.y));
    o.z = __uint_as_float(f2tf(v.z));
    o.w = __uint_as_float(f2tf(v.w));
    return o;
}
__device__ __forceinline__ float gelu_exact(float x) {
    return 0.5f * x * (1.0f + erff(x * 0.70710678118654752440f));
}
__device__ __forceinline__ void mma8(float* c, const unsigned* a, const unsigned* b) {
    asm("mma.sync.aligned.m16n8k8.row.col.f32.tf32.tf32.f32 "
        "{%0,%1,%2,%3}, {%4,%5,%6,%7}, {%8,%9}, {%0,%1,%2,%3};\n"
        : "+f"(c[0]), "+f"(c[1]), "+f"(c[2]), "+f"(c[3])
        : "r"(a[0]), "r"(a[1]), "r"(a[2]), "r"(a[3]), "r"(b[0]), "r"(b[1]));
}

// ============================================================
// Kernel 0: zero output + counters
// ============================================================
__global__ void zero_kernel(float* __restrict__ out) {
    int i = blockIdx.x * blockDim.x + threadIdx.x;
    if (i < T * H) out[i] = 0.0f;
    if (i < E) g_cnt[i] = 0;
}

// ============================================================
// Kernel 1: router — one warp per token
// ============================================================
__global__ void router_kernel(const float* __restrict__ X, const float* __restrict__ GW) {
    int warp = (blockIdx.x * blockDim.x + threadIdx.x) >> 5;
    int lane = threadIdx.x & 31;
    if (warp >= T) return;
    const float* x = X + (size_t)warp * H;

    float xr[32];
#pragma unroll
    for (int i = 0; i < 32; i++) xr[i] = x[lane + 32 * i];

    float logit[E];
#pragma unroll
    for (int e = 0; e < E; e++) {
        const float* gw = GW + (size_t)e * H;
        float s = 0.0f;
#pragma unroll
        for (int i = 0; i < 32; i++) s += xr[i] * gw[lane + 32 * i];
#pragma unroll
        for (int off = 16; off > 0; off >>= 1) s += __shfl_xor_sync(0xFFFFFFFFu, s, off);
        logit[e] = s;
    }

    if (lane == 0) {
        // argmax + second argmax on logits (same ordering as softmax probs)
        int e0 = 0;
        float l0 = logit[0];
#pragma unroll
        for (int e = 1; e < E; e++) if (logit[e] > l0) { l0 = logit[e]; e0 = e; }
        int e1 = -1;
        float l1 = -1e30f;
#pragma unroll
        for (int e = 0; e < E; e++) if (e != e0 && logit[e] > l1) { l1 = logit[e]; e1 = e; }

        // normalized top-2 weights: softmax denominators cancel
        float p0 = expf(l0 - l0);            // = 1
        float p1 = expf(l1 - l0);
        float inv = 1.0f / (p0 + p1);
        float w0 = p0 * inv, w1 = p1 * inv;

        int s0 = atomicAdd(&g_cnt[e0], 1);
        g_tok[e0 * T + s0]  = warp;
        g_prow[e0 * T + s0] = 2 * warp;
        g_w[e0 * T + s0]    = w0;
        int s1 = atomicAdd(&g_cnt[e1], 1);
        g_tok[e1 * T + s1]  = warp;
        g_prow[e1 * T + s1] = 2 * warp + 1;
        g_w[e1 * T + s1]    = w1;
    }
}

// ============================================================
// Kernel 2: grouped GEMM1 + GELU fusion
//   hact[prow, n] = up * gelu(gate),  n in [0, FF)
//   gate[m,n] = sum_k x[tok_m,k] * Wgu[e][n][k]
//   up  [m,n] = sum_k x[tok_m,k] * Wgu[e][FF+n][k]
// ============================================================
__global__ __launch_bounds__(256) void gemm1_kernel(
    const float* __restrict__ X, const float* __restrict__ GUW)
{
    int e   = blockIdx.z;
    int cnt = g_cnt[e];
    int m0  = blockIdx.y * BM;
    if (m0 >= cnt) return;
    int n0  = blockIdx.x * BN;

    __shared__ __align__(16) float As[2][BM * KP];
    __shared__ __align__(16) float Bgs[2][BN * KP];
    __shared__ __align__(16) float Bus[2][BN * KP];
    __shared__ int s_tok[BM];
    __shared__ int s_prow[BM];

    int tid = threadIdx.x;
    if (tid < BM) {
        int slot = m0 + tid;
        int v = (slot < cnt);
        s_tok[tid]  = v ? g_tok[e * T + slot]  : -1;
        s_prow[tid] = v ? g_prow[e * T + slot] : -1;
    }
    __syncthreads();

    const float* wgu = GUW + (size_t)e * (2 * FF) * H;
    int q = tid & 3, r = tid >> 2;          // loader coords: r 0..63, q 0..3
    int lane = tid & 31, w = tid >> 5;
    int wm = (w & 3) * 32, wn = (w >> 2) * 32;
    int g = lane >> 2, t4 = lane & 3;

    float gacc[2][4][4], uacc[2][4][4];
#pragma unroll
    for (int i = 0; i < 2; i++)
#pragma unroll
        for (int j = 0; j < 4; j++)
#pragma unroll
            for (int k = 0; k < 4; k++) { gacc[i][j][k] = 0.0f; uacc[i][j][k] = 0.0f; }

    float4 pa0, pa1, pbg, pbu;

#define LOADG1(KT) {                                                          \
    int k0_ = (KT) * BK + q * 4;                                              \
    int t0_ = s_tok[r];                                                       \
    pa0 = (t0_ >= 0) ? *(const float4*)(X + (size_t)t0_ * H + k0_)            \
                     : make_float4(0.f,0.f,0.f,0.f);                          \
    int t1_ = s_tok[r + 64];                                                  \
    pa1 = (t1_ >= 0) ? *(const float4*)(X + (size_t)t1_ * H + k0_)            \
                     : make_float4(0.f,0.f,0.f,0.f);                          \
    pbg = *(const float4*)(wgu + (size_t)(n0 + r) * H + k0_);                 \
    pbu = *(const float4*)(wgu + (size_t)(FF + n0 + r) * H + k0_);            \
}
#define STORE1(BUF) {                                                         \
    *(float4*)&As[BUF][r * KP + 4 * q]        = cv4(pa0);                     \
    *(float4*)&As[BUF][(r + 64) * KP + 4 * q] = cv4(pa1);                     \
    *(float4*)&Bgs[BUF][r * KP + 4 * q]       = cv4(pbg);                     \
    *(float4*)&Bus[BUF][r * KP + 4 * q]       = cv4(pbu);                     \
}

    LOADG1(0);
    STORE1(0);
    __syncthreads();

    const int nK = H / BK;   // 64
    for (int kt = 0; kt < nK; kt++) {
        int cur = kt & 1;
        if (kt + 1 < nK) LOADG1(kt + 1);

        const float* A  = As[cur];
        const float* BG = Bgs[cur];
        const float* BU = Bus[cur];
#pragma unroll
        for (int ks = 0; ks < 2; ks++) {
            int kb = ks * 8;
            unsigned a[2][4], bg[4][2], bu[4][2];
#pragma unroll
            for (int mi = 0; mi < 2; mi++) {
                int mb = wm + mi * 16;
                a[mi][0] = __float_as_uint(A[(mb + g)     * KP + kb + t4]);
                a[mi][1] = __float_as_uint(A[(mb + g + 8) * KP + kb + t4]);
                a[mi][2] = __float_as_uint(A[(mb + g)     * KP + kb + t4 + 4]);
                a[mi][3] = __float_as_uint(A[(mb + g + 8) * KP + kb + t4 + 4]);
            }
#pragma unroll
            for (int ni = 0; ni < 4; ni++) {
                int nb = wn + ni * 8 + g;
                bg[ni][0] = __float_as_uint(BG[nb * KP + kb + t4]);
                bg[ni][1] = __float_as_uint(BG[nb * KP + kb + t4 + 4]);
                bu[ni][0] = __float_as_uint(BU[nb * KP + kb + t4]);
                bu[ni][1] = __float_as_uint(BU[nb * KP + kb + t4 + 4]);
            }
#pragma unroll
            for (int mi = 0; mi < 2; mi++)
#pragma unroll
                for (int ni = 0; ni < 4; ni++) {
                    mma8(gacc[mi][ni], a[mi], bg[ni]);
                    mma8(uacc[mi][ni], a[mi], bu[ni]);
                }
        }
        if (kt + 1 < nK) STORE1(cur ^ 1);
        __syncthreads();
    }

    // epilogue: hact = up * gelu(gate)
#pragma unroll
    for (int mi = 0; mi < 2; mi++)
#pragma unroll
        for (int ni = 0; ni < 4; ni++) {
            int rl0 = wm + mi * 16 + g;
            int cl  = wn + ni * 8 + 2 * t4;
#pragma unroll
            for (int rr = 0; rr < 2; rr++) {
                int rl = rl0 + rr * 8;
                if (m0 + rl < cnt) {
                    int prow = s_prow[rl];
                    float h0 = uacc[mi][ni][rr * 2 + 0] * gelu_exact(gacc[mi][ni][rr * 2 + 0]);
                    float h1 = uacc[mi][ni][rr * 2 + 1] * gelu_exact(gacc[mi][ni][rr * 2 + 1]);
                    *(float2*)&g_hact[(size_t)prow * FF + n0 + cl] = make_float2(h0, h1);
                }
            }
        }
#undef LOADG1
#undef STORE1
}

// ============================================================
// Kernel 3: grouped GEMM2 + weighted scatter
//   out[t, n] += w * sum_f hact[prow, f] * down_w[e][n][f]
// ============================================================
__global__ __launch_bounds__(256) void gemm2_kernel(
    const float* __restrict__ DW, float* __restrict__ out)
{
    int e   = blockIdx.z;
    int cnt = g_cnt[e];
    int m0  = blockIdx.y * BM;
    if (m0 >= cnt) return;
    int n0  = blockIdx.x * BN;

    __shared__ __align__(16) float As[2][BM * KP];
    __shared__ __align__(16) float Bs[2][BN * KP];
    __shared__ int   s_prow[BM];
    __shared__ int   s_tok[BM];
    __shared__ float s_w[BM];

    int tid = threadIdx.x;
    if (tid < BM) {
        int slot = m0 + tid;
        int v = (slot < cnt);
        s_prow[tid] = v ? g_prow[e * T + slot] : -1;
        s_tok[tid]  = v ? g_tok[e * T + slot]  : 0;
        s_w[tid]    = v ? g_w[e * T + slot]    : 0.0f;
    }
    __syncthreads();

    const float* dw = DW + (size_t)e * H * FF;
    int q = tid & 3, r = tid >> 2;
    int lane = tid & 31, w = tid >> 5;
    int wm = (w & 3) * 32, wn = (w >> 2) * 32;
    int g = lane >> 2, t4 = lane & 3;

    float acc[2][4][4];
#pragma unroll
    for (int i = 0; i < 2; i++)
#pragma unroll
        for (int j = 0; j < 4; j++)
#pragma unroll
            for (int k = 0; k < 4; k++) acc[i][j][k] = 0.0f;

    float4 pa0, pa1, pb;

#define LOADG2(KT) {                                                          \
    int k0_ = (KT) * BK + q * 4;                                              \
    int p0_ = s_prow[r];                                                      \
    pa0 = (p0_ >= 0) ? *(const float4*)(g_hact + (size_t)p0_ * FF + k0_)      \
                     : make_float4(0.f,0.f,0.f,0.f);                          \
    int p1_ = s_prow[r + 64];                                                 \
    pa1 = (p1_ >= 0) ? *(const float4*)(g_hact + (size_t)p1_ * FF + k0_)      \
                     : make_float4(0.f,0.f,0.f,0.f);                          \
    pb  = *(const float4*)(dw + (size_t)(n0 + r) * FF + k0_);                 \
}
#define STORE2(BUF) {                                                         \
    *(float4*)&As[BUF][r * KP + 4 * q]        = cv4(pa0);                     \
    *(float4*)&As[BUF][(r + 64) * KP + 4 * q] = cv4(pa1);                     \
    *(float4*)&Bs[BUF][r * KP + 4 * q]        = cv4(pb);                      \
}

    LOADG2(0);
    STORE2(0);
    __syncthreads();

    const int nK = FF / BK;   // 256
    for (int kt = 0; kt < nK; kt++) {
        int cur = kt & 1;
        if (kt + 1 < nK) LOADG2(kt + 1);

        const float* A = As[cur];
        const float* B = Bs[cur];
#pragma unroll
        for (int ks = 0; ks < 2; ks++) {
            int kb = ks * 8;
            unsigned a[2][4], b[4][2];
#pragma unroll
            for (int mi = 0; mi < 2; mi++) {
                int mb = wm + mi * 16;
                a[mi][0] = __float_as_uint(A[(mb + g)     * KP + kb + t4]);
                a[mi][1] = __float_as_uint(A[(mb + g + 8) * KP + kb + t4]);
                a[mi][2] = __float_as_uint(A[(mb + g)     * KP + kb + t4 + 4]);
                a[mi][3] = __float_as_uint(A[(mb + g + 8) * KP + kb + t4 + 4]);
            }
#pragma unroll
            for (int ni = 0; ni < 4; ni++) {
                int nb = wn + ni * 8 + g;
                b[ni][0] = __float_as_uint(B[nb * KP + kb + t4]);
                b[ni][1] = __float_as_uint(B[nb * KP + kb + t4 + 4]);
            }
#pragma unroll
            for (int mi = 0; mi < 2; mi++)
#pragma unroll
                for (int ni = 0; ni < 4; ni++)
                    mma8(acc[mi][ni], a[mi], b[ni]);
        }
        if (kt + 1 < nK) STORE2(cur ^ 1);
        __syncthreads();
    }

    // epilogue: weighted atomic scatter into out[t, n]
#pragma unroll
    for (int mi = 0; mi < 2; mi++)
#pragma unroll
        for (int ni = 0; ni < 4; ni++) {
            int rl0 = wm + mi * 16 + g;
            int cl  = wn + ni * 8 + 2 * t4;
#pragma unroll
            for (int rr = 0; rr < 2; rr++) {
                int rl = rl0 + rr * 8;
                if (m0 + rl < cnt) {
                    int   t  = s_tok[rl];
                    float wt = s_w[rl];
                    atomicAdd(&out[(size_t)t * H + n0 + cl],     wt * acc[mi][ni][rr * 2 + 0]);
                    atomicAdd(&out[(size_t)t * H + n0 + cl + 1], wt * acc[mi][ni][rr * 2 + 1]);
                }
            }
        }
#undef LOADG2
#undef STORE2
}

// ============================================================
extern "C" void kernel_launch(void* const* d_in, const int* in_sizes, int n_in,
                              void* d_out, int out_size) {
    (void)in_sizes; (void)n_in; (void)out_size;
    const float* X   = (const float*)d_in[0];   // hidden_states (1,2048,1024)
    const float* GW  = (const float*)d_in[1];   // gate_w (8,1024)
    const float* GUW = (const float*)d_in[2];   // gate_up_w (8,8192,1024)
    const float* DW  = (const float*)d_in[3];   // down_w (8,1024,4096)
    float* out = (float*)d_out;                 // (1,2048,1024) fp32

    zero_kernel<<<(T * H + 255) / 256, 256>>>(out);
    router_kernel<<<T / 8, 256>>>(X, GW);
    gemm1_kernel<<<dim3(FF / BN, T / BM, E), 256>>>(X, GUW);
    gemm2_kernel<<<dim3(H / BN, T / BM, E), 256>>>(DW, out);
}